// round 1
// baseline (speedup 1.0000x reference)
#include <cuda_runtime.h>

// Optimal-transport (Sinkhorn) loss on 64x64 pooled grids.
// Key identity: K = exp(-C/0.1) on a 2D grid with squared-euclidean cost is a
// separable stencil exp(-10*dy^2)*exp(-10*dx^2); taps |d|>=3 underflow fp32
// relevance (< 1e-34 relative). So K@v and (K*C)@v are 5x5 separable stencils.
// One CTA per batch image; u, v, tmp live in shared memory for all 50 iters.

#define GS     64            // pooled grid side
#define STR    72            // padded row stride (floats), 32B-aligned
#define ITERS  50
#define NBATCH 16
#define EPS    1e-8f

// e^{-10*d^2} taps
#define W1 4.5399929762484854e-05f   // exp(-10)
#define W0 4.2483542552915889e-18f   // exp(-40)
// d^2 * e^{-10*d^2} taps (for M = K*C), center = 0
#define G1 4.5399929762484854e-05f
#define G0 1.6993417021166356e-17f   // 4*exp(-40)

// shared-memory layout (floats)
#define OFF_U   0                    // 64 x 72
#define OFF_V   4608                 // 64 x 72
#define OFF_T1  9216                 // 68 x 72 (rows padded +-2)
#define OFF_T2  14112                // 68 x 72
#define OFF_RED 19008                // 64 floats reduction scratch
#define SM_FLOATS 19072

#define SU(r,c)  sm[OFF_U  + (r)*STR + (c) + 2]
#define SV(r,c)  sm[OFF_V  + (r)*STR + (c) + 2]
#define ST1(r,c) sm[OFF_T1 + ((r)+2)*STR + (c)]
#define ST2(r,c) sm[OFF_T2 + ((r)+2)*STR + (c)]

__device__ float g_costs[NBATCH];

__device__ __forceinline__ float blockReduceSum(float val, float* red) {
    const unsigned m = 0xffffffffu;
#pragma unroll
    for (int o = 16; o; o >>= 1) val += __shfl_xor_sync(m, val, o);
    const int w = threadIdx.x >> 5, l = threadIdx.x & 31;
    __syncthreads();               // guard reuse of red
    if (l == 0) red[w] = val;
    __syncthreads();
    if (w == 0) {
        float v = red[l];
#pragma unroll
        for (int o = 16; o; o >>= 1) v += __shfl_xor_sync(m, v, o);
        if (l == 0) red[0] = v;
    }
    __syncthreads();
    return red[0];
}

__global__ __launch_bounds__(1024, 1)
void ot_sinkhorn_kernel(const float* __restrict__ pred,
                        const float* __restrict__ gt) {
    extern __shared__ float sm[];
    const int t   = threadIdx.x;
    const int bid = blockIdx.x;

    // V-pass / register layout: one column, 4 consecutive rows per thread
    const int c  = t & 63;
    const int r0 = (t >> 6) << 2;
    // H-pass layout: one row, 4 consecutive cols per thread
    const int hr  = t >> 4;
    const int hc0 = (t & 15) << 2;

    // zero everything (padding must be 0)
    for (int i = t; i < SM_FLOATS; i += 1024) sm[i] = 0.f;
    __syncthreads();

    // ---- 8x8 sum-pooling (== avg_pool * d^2), held in registers (V layout) ----
    float areg[4], breg[4];
    float asum = 0.f, bsum = 0.f;
    const float* pb = pred + (size_t)bid * 262144;   // 512*512
    const float* gb = gt   + (size_t)bid * 262144;
#pragma unroll
    for (int i = 0; i < 4; ++i) {
        const int rp = r0 + i;
        const float4* prow = (const float4*)(pb + (size_t)rp * 8 * 512 + c * 8);
        const float4* grow = (const float4*)(gb + (size_t)rp * 8 * 512 + c * 8);
        float sa = 0.f, sb = 0.f;
#pragma unroll
        for (int yy = 0; yy < 8; ++yy) {
            float4 a0 = prow[yy * 128 + 0];
            float4 a1 = prow[yy * 128 + 1];
            sa += (a0.x + a0.y) + (a0.z + a0.w) + (a1.x + a1.y) + (a1.z + a1.w);
            float4 b0 = grow[yy * 128 + 0];
            float4 b1 = grow[yy * 128 + 1];
            sb += (b0.x + b0.y) + (b0.z + b0.w) + (b1.x + b1.y) + (b1.z + b1.w);
        }
        areg[i] = sa; breg[i] = sb;
        asum += sa;  bsum += sb;
    }
    asum = blockReduceSum(asum, sm + OFF_RED);
    bsum = blockReduceSum(bsum, sm + OFF_RED);
    const float ra = 1.f / fmaxf(asum, 1e-8f);
    const float rb = 1.f / fmaxf(bsum, 1e-8f);
#pragma unroll
    for (int i = 0; i < 4; ++i) { areg[i] *= ra; breg[i] *= rb; }

    // init u = 1 (interior only)
#pragma unroll
    for (int i = 0; i < 4; ++i) SU(r0 + i, c) = 1.f;
    __syncthreads();

    // ---- 50 Sinkhorn iterations ----
    for (int it = 0; it < ITERS; ++it) {
        // T1 = He(u)  (x-direction, e-taps)
        {
            float w[8];
#pragma unroll
            for (int j = 0; j < 8; ++j) w[j] = SU(hr, hc0 - 2 + j);
#pragma unroll
            for (int i = 0; i < 4; ++i)
                ST1(hr, hc0 + i) = w[i + 2] + W1 * (w[i + 1] + w[i + 3])
                                            + W0 * (w[i]     + w[i + 4]);
        }
        __syncthreads();
        // v = b / (Ve(T1) + eps)
        {
            float w[8];
#pragma unroll
            for (int j = 0; j < 8; ++j) w[j] = ST1(r0 - 2 + j, c);
#pragma unroll
            for (int i = 0; i < 4; ++i) {
                float s = w[i + 2] + W1 * (w[i + 1] + w[i + 3])
                                   + W0 * (w[i]     + w[i + 4]);
                SV(r0 + i, c) = breg[i] / (s + EPS);
            }
        }
        __syncthreads();
        // T1 = He(v)
        {
            float w[8];
#pragma unroll
            for (int j = 0; j < 8; ++j) w[j] = SV(hr, hc0 - 2 + j);
#pragma unroll
            for (int i = 0; i < 4; ++i)
                ST1(hr, hc0 + i) = w[i + 2] + W1 * (w[i + 1] + w[i + 3])
                                            + W0 * (w[i]     + w[i + 4]);
        }
        __syncthreads();
        // u = a / (Ve(T1) + eps)
        {
            float w[8];
#pragma unroll
            for (int j = 0; j < 8; ++j) w[j] = ST1(r0 - 2 + j, c);
#pragma unroll
            for (int i = 0; i < 4; ++i) {
                float s = w[i + 2] + W1 * (w[i + 1] + w[i + 3])
                                   + W0 * (w[i]     + w[i + 4]);
                SU(r0 + i, c) = areg[i] / (s + EPS);
            }
        }
        __syncthreads();
    }

    // ---- cost = u . (M v),  M v = Vg(He v) + Ve(Hg v) ----
    {
        float w[8];
#pragma unroll
        for (int j = 0; j < 8; ++j) w[j] = SV(hr, hc0 - 2 + j);
#pragma unroll
        for (int i = 0; i < 4; ++i) {
            ST1(hr, hc0 + i) = w[i + 2] + W1 * (w[i + 1] + w[i + 3])
                                        + W0 * (w[i]     + w[i + 4]);   // He(v)
            ST2(hr, hc0 + i) = G1 * (w[i + 1] + w[i + 3])
                             + G0 * (w[i]     + w[i + 4]);              // Hg(v)
        }
    }
    __syncthreads();
    float local = 0.f;
    {
        float w1[8], w2[8];
#pragma unroll
        for (int j = 0; j < 8; ++j) {
            w1[j] = ST1(r0 - 2 + j, c);
            w2[j] = ST2(r0 - 2 + j, c);
        }
#pragma unroll
        for (int i = 0; i < 4; ++i) {
            float mv = G1 * (w1[i + 1] + w1[i + 3])                     // Vg(He v)
                     + G0 * (w1[i]     + w1[i + 4])
                     + w2[i + 2] + W1 * (w2[i + 1] + w2[i + 3])         // Ve(Hg v)
                                 + W0 * (w2[i]     + w2[i + 4]);
            local += SU(r0 + i, c) * mv;
        }
    }
    float cost = blockReduceSum(local, sm + OFF_RED);
    if (t == 0) {
        bool valid = (asum > 0.5f) && (bsum > 0.5f);
        g_costs[bid] = valid ? cost : 0.f;
    }
}

__global__ void ot_finalize_kernel(float* __restrict__ out) {
    float s = 0.f;
#pragma unroll
    for (int i = 0; i < NBATCH; ++i) s += g_costs[i];
    out[0] = s * (1.f / (float)NBATCH);
}

extern "C" void kernel_launch(void* const* d_in, const int* in_sizes, int n_in,
                              void* d_out, int out_size) {
    (void)in_sizes; (void)n_in; (void)out_size;
    const float* pred = (const float*)d_in[0];
    const float* gt   = (const float*)d_in[1];
    cudaFuncSetAttribute(ot_sinkhorn_kernel,
                         cudaFuncAttributeMaxDynamicSharedMemorySize,
                         SM_FLOATS * sizeof(float));
    ot_sinkhorn_kernel<<<NBATCH, 1024, SM_FLOATS * sizeof(float)>>>(pred, gt);
    ot_finalize_kernel<<<1, 1>>>((float*)d_out);
}

// round 2
// speedup vs baseline: 2.2638x; 2.2638x over previous
#include <cuda_runtime.h>

// Sinkhorn OT loss. K = exp(-C/0.1) on a 64x64 grid separates into 3-tap
// stencils per axis (taps |d|>=2 are < 4.3e-18 relative -> below fp32
// significance). Pipeline:
//   pool_kernel   : 512 CTAs, full-chip HBM bandwidth, 8x8 sum-pool -> g_pooled
//   sinkhorn_kernel: 16 CTAs (1/batch), fields live in registers (4x4/thread),
//                    horizontal pass via warp shuffles, vertical halos via
//                    double-buffered smem, 1 barrier per half-step.
// Finalize folded into sinkhorn via last-CTA pattern (deterministic order).

#define NBATCH 16
#define ITERS  50
#define EPS    1e-8f
#define W1     4.5399929762484854e-05f   // exp(-10); also d^2*exp(-10*d^2) at d=1

__device__ float g_pooled[2][NBATCH][4096];
__device__ float g_costs[NBATCH];
__device__ int   g_done;

// ---------------------------------------------------------------- pooling
__global__ __launch_bounds__(256) void pool_kernel(const float* __restrict__ pred,
                                                   const float* __restrict__ gt) {
    const int bid    = blockIdx.x;          // 0..511
    const int tensor = bid >> 8;            // 0 = pred, 1 = gt
    const int batch  = (bid >> 4) & 15;
    const int rb     = bid & 15;            // block of 4 pooled rows
    const float* src = (tensor ? gt : pred) + (size_t)batch * 262144;

    const int pr = rb * 4 + (threadIdx.x >> 6);   // pooled row 0..63
    const int pc = threadIdx.x & 63;              // pooled col 0..63
    const float4* p = (const float4*)(src + (size_t)pr * 4096 + pc * 8);

    float s = 0.f;
#pragma unroll
    for (int y = 0; y < 8; ++y) {
        float4 v0 = p[y * 128];
        float4 v1 = p[y * 128 + 1];
        s += (v0.x + v0.y) + (v0.z + v0.w) + (v1.x + v1.y) + (v1.z + v1.w);
    }
    g_pooled[tensor][batch][pr * 64 + pc] = s;
}

// ---------------------------------------------------------------- sinkhorn
__device__ __forceinline__ float blockReduceSum(float val, float* red) {
#pragma unroll
    for (int o = 16; o; o >>= 1) val += __shfl_xor_sync(0xffffffffu, val, o);
    const int w = threadIdx.x >> 5, l = threadIdx.x & 31;
    __syncthreads();
    if (l == 0) red[w] = val;
    __syncthreads();
    float s = ((red[0] + red[1]) + (red[2] + red[3]))
            + ((red[4] + red[5]) + (red[6] + red[7]));
    __syncthreads();
    return s;
}

// one half-step: out = tgt / (Ve(He(in)) + eps)
// thread owns rows 4*band..4*band+3, cols c0..c0+3 (band = 16-lane segment)
__device__ __forceinline__ void halfstep(
    float (&out)[4][4], const float (&tgt)[4][4], const float (&in)[4][4],
    int buf, int band, int c0, int seg,
    float (*htop)[17][64], float (*hbot)[17][64])
{
    float H[4][4];
#pragma unroll
    for (int i = 0; i < 4; ++i) {
        float lf = __shfl_up_sync(0xffffffffu, in[i][3], 1, 16);
        float rt = __shfl_down_sync(0xffffffffu, in[i][0], 1, 16);
        if (seg == 0)  lf = 0.f;
        if (seg == 15) rt = 0.f;
        H[i][0] = fmaf(W1, lf + in[i][1],        in[i][0]);
        H[i][1] = fmaf(W1, in[i][0] + in[i][2],  in[i][1]);
        H[i][2] = fmaf(W1, in[i][1] + in[i][3],  in[i][2]);
        H[i][3] = fmaf(W1, in[i][2] + rt,        in[i][3]);
    }
    *(float4*)&htop[buf][band][c0]     = make_float4(H[0][0], H[0][1], H[0][2], H[0][3]);
    *(float4*)&hbot[buf][band + 1][c0] = make_float4(H[3][0], H[3][1], H[3][2], H[3][3]);
    __syncthreads();
    const float4 up = *(const float4*)&hbot[buf][band][c0];      // row 4b-1 (0 if b==0)
    const float4 dn = *(const float4*)&htop[buf][band + 1][c0];  // row 4b+4 (0 if b==15)
    const float upv[4] = {up.x, up.y, up.z, up.w};
    const float dnv[4] = {dn.x, dn.y, dn.z, dn.w};
#pragma unroll
    for (int i = 0; i < 4; ++i) {
#pragma unroll
        for (int j = 0; j < 4; ++j) {
            const float ab = (i == 0) ? upv[j] : H[i - 1][j];
            const float be = (i == 3) ? dnv[j] : H[i + 1][j];
            const float s  = fmaf(W1, ab + be, H[i][j]) + EPS;
            out[i][j] = __fdividef(tgt[i][j], s);
        }
    }
}

__global__ __launch_bounds__(256, 1) void sinkhorn_kernel(float* __restrict__ out) {
    __shared__ float htop[2][17][64];
    __shared__ float hbot[2][17][64];
    __shared__ float red[8];

    const int t    = threadIdx.x;
    const int w    = t >> 5, l = t & 31;
    const int seg  = l & 15;
    const int band = 2 * w + (l >> 4);   // 0..15, 4 rows each
    const int c0   = seg * 4;
    const int bid  = blockIdx.x;

    // permanent zero-pad halo rows (never overwritten: stores hit htop[0..15], hbot[1..16])
    if (t < 64) {
        htop[0][16][t] = 0.f; htop[1][16][t] = 0.f;
        hbot[0][0][t]  = 0.f; hbot[1][0][t]  = 0.f;
    }

    float a[4][4], b[4][4], u[4][4], v[4][4];
    float asum = 0.f, bsum = 0.f;
    const float* pa = g_pooled[0][bid];
    const float* pb = g_pooled[1][bid];
#pragma unroll
    for (int i = 0; i < 4; ++i) {
        const float4 x = *(const float4*)(pa + (band * 4 + i) * 64 + c0);
        const float4 y = *(const float4*)(pb + (band * 4 + i) * 64 + c0);
        a[i][0] = x.x; a[i][1] = x.y; a[i][2] = x.z; a[i][3] = x.w;
        b[i][0] = y.x; b[i][1] = y.y; b[i][2] = y.z; b[i][3] = y.w;
        asum += (x.x + x.y) + (x.z + x.w);
        bsum += (y.x + y.y) + (y.z + y.w);
    }
    asum = blockReduceSum(asum, red);
    bsum = blockReduceSum(bsum, red);
    const float ra  = 1.f / fmaxf(asum, 1e-8f);
    const float rbv = 1.f / fmaxf(bsum, 1e-8f);
#pragma unroll
    for (int i = 0; i < 4; ++i)
#pragma unroll
        for (int j = 0; j < 4; ++j) {
            a[i][j] *= ra; b[i][j] *= rbv; u[i][j] = 1.f;
        }
    __syncthreads();   // pad rows + normalized state visible

    // ---- 50 iterations: v = b/(K u); u = a/(K v) ----
    for (int it = 0; it < ITERS; ++it) {
        halfstep(v, b, u, 0, band, c0, seg, htop, hbot);
        halfstep(u, a, v, 1, band, c0, seg, htop, hbot);
    }

    // ---- cost = u . (M v);  Mv = Hg(v) + W1*(T_above + T_below), T = He+Hg = v + 2*Hg
    float HG[4][4];
#pragma unroll
    for (int i = 0; i < 4; ++i) {
        float lf = __shfl_up_sync(0xffffffffu, v[i][3], 1, 16);
        float rt = __shfl_down_sync(0xffffffffu, v[i][0], 1, 16);
        if (seg == 0)  lf = 0.f;
        if (seg == 15) rt = 0.f;
        HG[i][0] = W1 * (lf + v[i][1]);
        HG[i][1] = W1 * (v[i][0] + v[i][2]);
        HG[i][2] = W1 * (v[i][1] + v[i][3]);
        HG[i][3] = W1 * (v[i][2] + rt);
    }
    float T[4][4];
#pragma unroll
    for (int i = 0; i < 4; ++i)
#pragma unroll
        for (int j = 0; j < 4; ++j) T[i][j] = fmaf(2.f, HG[i][j], v[i][j]);

    *(float4*)&htop[0][band][c0]     = make_float4(T[0][0], T[0][1], T[0][2], T[0][3]);
    *(float4*)&hbot[0][band + 1][c0] = make_float4(T[3][0], T[3][1], T[3][2], T[3][3]);
    __syncthreads();
    const float4 up = *(const float4*)&hbot[0][band][c0];
    const float4 dn = *(const float4*)&htop[0][band + 1][c0];
    const float upv[4] = {up.x, up.y, up.z, up.w};
    const float dnv[4] = {dn.x, dn.y, dn.z, dn.w};

    float local = 0.f;
#pragma unroll
    for (int i = 0; i < 4; ++i) {
#pragma unroll
        for (int j = 0; j < 4; ++j) {
            const float ab = (i == 0) ? upv[j] : T[i - 1][j];
            const float be = (i == 3) ? dnv[j] : T[i + 1][j];
            const float mv = fmaf(W1, ab + be, HG[i][j]);
            local = fmaf(u[i][j], mv, local);
        }
    }
    const float cost = blockReduceSum(local, red);

    if (t == 0) {
        const bool valid = (asum > 0.5f) && (bsum > 0.5f);
        g_costs[bid] = valid ? cost : 0.f;
        __threadfence();
        const int prev = atomicAdd(&g_done, 1);
        if (prev == NBATCH - 1) {
            g_done = 0;                 // reset for next graph replay
            __threadfence();
            float s = 0.f;
#pragma unroll
            for (int i = 0; i < NBATCH; ++i) s += g_costs[i];
            out[0] = s * (1.f / (float)NBATCH);
        }
    }
}

extern "C" void kernel_launch(void* const* d_in, const int* in_sizes, int n_in,
                              void* d_out, int out_size) {
    (void)in_sizes; (void)n_in; (void)out_size;
    const float* pred = (const float*)d_in[0];
    const float* gt   = (const float*)d_in[1];
    pool_kernel<<<512, 256>>>(pred, gt);
    sinkhorn_kernel<<<NBATCH, 256>>>((float*)d_out);
}